// round 5
// baseline (speedup 1.0000x reference)
#include <cuda_runtime.h>

#define DIM 256
#define RPB 16          // batch rows per CTA
#define NTH 512         // one output column (of 2D=512) per thread
#define KMAX 64

__global__ __launch_bounds__(NTH, 3)
void easyrec_fused(const int* __restrict__ nodes_u,
                   const int* __restrict__ nodes_v,
                   const int* __restrict__ neighbors,
                   const int* __restrict__ neighbor_counts,
                   const float* __restrict__ u2e,
                   const float* __restrict__ v2e,
                   const float* __restrict__ W,     // [D, 2D] row-major
                   const float* __restrict__ bvec,  // [D]
                   float* __restrict__ out,
                   int B)
{
    __shared__ float sv [RPB][DIM];     // gathered v2e rows           16 KB
    __shared__ float snl[RPB][DIM];     // lower-half neighbor sums    16 KB
    __shared__ int   snb[RPB][KMAX];    // neighbor indices             4 KB
    __shared__ int   scnt[RPB];
    __shared__ int   su[RPB];
    __shared__ int   svi[RPB];
    __shared__ float sred[RPB][NTH / 32];

    const int t    = threadIdx.x;
    const int wid  = t >> 5;
    const int row0 = blockIdx.x * RPB;

    // ---- metadata first ----
    if (t < RPB) {
        int b = row0 + t; if (b >= B) b = B - 1;
        scnt[t] = neighbor_counts[b];
        su[t]   = nodes_u[b];
        svi[t]  = nodes_v[b];
    }
    __syncthreads();

    // ---- Phase A: v tile + neighbor indices (coalesced) ----
    #pragma unroll
    for (int i = t; i < RPB * DIM; i += NTH) {
        int r = i >> 8, c = i & (DIM - 1);
        sv[r][c] = v2e[(size_t)svi[r] * DIM + c];
    }
    #pragma unroll
    for (int i = t; i < RPB * KMAX; i += NTH) {
        int r = i >> 6, k = i & (KMAX - 1);
        int b = row0 + r; if (b >= B) b = B - 1;
        snb[r][k] = neighbors[(size_t)b * KMAX + k];
    }
    __syncthreads();

    // ---- Lower half: gather FIRST half of neighbors (before GEMM) ----
    if (t < DIM) {
        #pragma unroll 1
        for (int r = 0; r < RPB; r++) {
            const int h  = scnt[r] >> 1;
            const int* nb = snb[r];
            float n0 = 0.f, n1 = 0.f, n2 = 0.f, n3 = 0.f;
            int k = 0;
            #pragma unroll 1
            for (; k + 4 <= h; k += 4) {
                n0 += u2e[(size_t)nb[k + 0] * DIM + t];
                n1 += u2e[(size_t)nb[k + 1] * DIM + t];
                n2 += u2e[(size_t)nb[k + 2] * DIM + t];
                n3 += u2e[(size_t)nb[k + 3] * DIM + t];
            }
            #pragma unroll 1
            for (; k < h; k++) n0 += u2e[(size_t)nb[k] * DIM + t];
            snl[r][t] = (n0 + n1) + (n2 + n3);
        }
    }

    // ---- GEMM: G[r][t] = sum_j v[r][j] * W[j][t]  (thread owns col t of 512) ----
    float acc[RPB];
    #pragma unroll
    for (int r = 0; r < RPB; r++) acc[r] = 0.f;

    const float* Wc = W + t;
    #pragma unroll 1
    for (int j = 0; j < DIM; j += 4) {
        float w0 = Wc[(size_t)(j + 0) * (2 * DIM)];
        float w1 = Wc[(size_t)(j + 1) * (2 * DIM)];
        float w2 = Wc[(size_t)(j + 2) * (2 * DIM)];
        float w3 = Wc[(size_t)(j + 3) * (2 * DIM)];
        #pragma unroll
        for (int r = 0; r < RPB; r++) {
            float4 v4 = *reinterpret_cast<const float4*>(&sv[r][j]);  // broadcast LDS.128
            acc[r] = fmaf(v4.x, w0, acc[r]);
            acc[r] = fmaf(v4.y, w1, acc[r]);
            acc[r] = fmaf(v4.z, w2, acc[r]);
            acc[r] = fmaf(v4.w, w3, acc[r]);
        }
    }
    __syncthreads();    // snl visible to upper half; acc ready

    const float bt = (t < DIM) ? bvec[t] : 0.f;

    // ---- Combine: fully unrolled (static acc indexing, no local spills) ----
    #pragma unroll
    for (int r = 0; r < RPB; r++) {
        const int cnt = scnt[r];
        float partial;
        if (t < DIM) {
            // cols 0..255: self . g1  + bias . v   (or fallback self . v)
            const float selfv = u2e[(size_t)su[r] * DIM + t];
            partial = (cnt > 0) ? selfv * acc[r] + bt * sv[r][t]
                                : selfv * sv[r][t];
        } else {
            // cols 256..511: nmean . g2 ; gather SECOND half of neighbors here
            const int c = t - DIM;
            if (cnt > 0) {
                const int h  = cnt >> 1;
                const int* nb = snb[r];
                float n0 = 0.f, n1 = 0.f, n2 = 0.f, n3 = 0.f;
                int k = h;
                #pragma unroll 1
                for (; k + 4 <= cnt; k += 4) {
                    n0 += u2e[(size_t)nb[k + 0] * DIM + c];
                    n1 += u2e[(size_t)nb[k + 1] * DIM + c];
                    n2 += u2e[(size_t)nb[k + 2] * DIM + c];
                    n3 += u2e[(size_t)nb[k + 3] * DIM + c];
                }
                #pragma unroll 1
                for (; k < cnt; k++) n0 += u2e[(size_t)nb[k] * DIM + c];
                const float nsum = snl[r][c] + ((n0 + n1) + (n2 + n3));
                partial = nsum * (1.f / (float)cnt) * acc[r];
            } else {
                partial = 0.f;
            }
        }
        #pragma unroll
        for (int o = 16; o; o >>= 1)
            partial += __shfl_down_sync(0xffffffffu, partial, o);
        if ((t & 31) == 0) sred[r][wid] = partial;
    }
    __syncthreads();

    if (t < RPB) {
        float s = 0.f;
        #pragma unroll
        for (int w = 0; w < NTH / 32; w++) s += sred[t][w];
        if (row0 + t < B) out[row0 + t] = s;
    }
}

extern "C" void kernel_launch(void* const* d_in, const int* in_sizes, int n_in,
                              void* d_out, int out_size)
{
    const int*   nodes_u         = (const int*)  d_in[0];
    const int*   nodes_v         = (const int*)  d_in[1];
    const int*   neighbors       = (const int*)  d_in[2];
    const int*   neighbor_counts = (const int*)  d_in[3];
    const float* u2e             = (const float*)d_in[4];
    const float* v2e             = (const float*)d_in[5];
    const float* W               = (const float*)d_in[6];
    const float* bvec            = (const float*)d_in[7];
    float*       out             = (float*)d_out;

    const int B = in_sizes[0];
    const int grid = (B + RPB - 1) / RPB;
    easyrec_fused<<<grid, NTH>>>(nodes_u, nodes_v, neighbors, neighbor_counts,
                                 u2e, v2e, W, bvec, out, B);
}

// round 6
// speedup vs baseline: 1.3505x; 1.3505x over previous
#include <cuda_runtime.h>

#define DIM 256
#define RPB 16          // rows (batch elements) per CTA
#define NTHREADS 256
#define KMAX 64

__global__ __launch_bounds__(NTHREADS, 4)
void easyrec_fused(const int* __restrict__ nodes_u,
                   const int* __restrict__ nodes_v,
                   const int* __restrict__ neighbors,
                   const int* __restrict__ neighbor_counts,
                   const float* __restrict__ u2e,
                   const float* __restrict__ v2e,
                   const float* __restrict__ W,     // [D, 2D] row-major
                   const float* __restrict__ bvec,  // [D]
                   float* __restrict__ out,
                   int B)
{
    __shared__ float sv[RPB][DIM];      // gathered v2e rows      16 KB
    __shared__ int   snb[RPB][KMAX];    // neighbor indices        4 KB
    __shared__ int   scnt[RPB];
    __shared__ int   su[RPB];
    __shared__ float sred[RPB][8];      // warp partials

    const int t    = threadIdx.x;
    const int row0 = blockIdx.x * RPB;

    // ---- Phase A: load v tile + metadata (clamped for tail safety) ----
    #pragma unroll
    for (int r = 0; r < RPB; r++) {
        int b  = row0 + r; if (b >= B) b = B - 1;
        int vi = nodes_v[b];
        sv[r][t] = v2e[(size_t)vi * DIM + t];
    }
    for (int i = t; i < RPB * KMAX; i += NTHREADS) {
        int r = i >> 6, k = i & 63;
        int b = row0 + r; if (b >= B) b = B - 1;
        snb[r][k] = neighbors[(size_t)b * KMAX + k];
    }
    if (t < RPB) {
        int b = row0 + t; if (b >= B) b = B - 1;
        scnt[t] = neighbor_counts[b];
        su[t]   = nodes_u[b];
    }
    __syncthreads();

    // ---- Phase B: g[r] = v[r] @ W. Thread t owns cols t and t+256.
    //      Software-pipelined W loads: next iteration's 8 values prefetched
    //      into registers while this iteration's FFMAs run.
    float acc1[RPB], acc2[RPB];
    #pragma unroll
    for (int r = 0; r < RPB; r++) { acc1[r] = 0.f; acc2[r] = 0.f; }

    const float* Wc = W + t;
    // preload j = 0 chunk
    float p0 = Wc[0 * (2 * DIM)];
    float p1 = Wc[1 * (2 * DIM)];
    float p2 = Wc[2 * (2 * DIM)];
    float p3 = Wc[3 * (2 * DIM)];
    float p4 = Wc[0 * (2 * DIM) + DIM];
    float p5 = Wc[1 * (2 * DIM) + DIM];
    float p6 = Wc[2 * (2 * DIM) + DIM];
    float p7 = Wc[3 * (2 * DIM) + DIM];

    #pragma unroll 1
    for (int j = 0; j < DIM; j += 4) {
        const float w1a = p0, w1b = p1, w1c = p2, w1d = p3;
        const float w2a = p4, w2b = p5, w2c = p6, w2d = p7;
        if (j + 4 < DIM) {
            const float* wn = Wc + (size_t)(j + 4) * (2 * DIM);
            p0 = wn[0 * (2 * DIM)];
            p1 = wn[1 * (2 * DIM)];
            p2 = wn[2 * (2 * DIM)];
            p3 = wn[3 * (2 * DIM)];
            p4 = wn[0 * (2 * DIM) + DIM];
            p5 = wn[1 * (2 * DIM) + DIM];
            p6 = wn[2 * (2 * DIM) + DIM];
            p7 = wn[3 * (2 * DIM) + DIM];
        }
        #pragma unroll
        for (int r = 0; r < RPB; r++) {
            float4 v4 = *reinterpret_cast<const float4*>(&sv[r][j]);   // broadcast LDS.128
            acc1[r] = fmaf(v4.x, w1a, acc1[r]);
            acc1[r] = fmaf(v4.y, w1b, acc1[r]);
            acc1[r] = fmaf(v4.z, w1c, acc1[r]);
            acc1[r] = fmaf(v4.w, w1d, acc1[r]);
            acc2[r] = fmaf(v4.x, w2a, acc2[r]);
            acc2[r] = fmaf(v4.y, w2b, acc2[r]);
            acc2[r] = fmaf(v4.z, w2c, acc2[r]);
            acc2[r] = fmaf(v4.w, w2d, acc2[r]);
        }
    }

    const float bt = bvec[t];

    // ---- Phase C: FULLY UNROLLED over r -> static acc indexing, no
    //      local-memory spill of acc1/acc2. ----
    #pragma unroll
    for (int r = 0; r < RPB; r++) {
        const int   cnt   = scnt[r];
        const float selfv = u2e[(size_t)su[r] * DIM + t];   // coalesced
        const float vrt   = sv[r][t];
        float partial;
        if (cnt > 0) {
            const int* nb = snb[r];
            float n0 = 0.f, n1 = 0.f, n2 = 0.f, n3 = 0.f;
            int k = 0;
            #pragma unroll 1
            for (; k + 4 <= cnt; k += 4) {
                n0 += u2e[(size_t)nb[k + 0] * DIM + t];
                n1 += u2e[(size_t)nb[k + 1] * DIM + t];
                n2 += u2e[(size_t)nb[k + 2] * DIM + t];
                n3 += u2e[(size_t)nb[k + 3] * DIM + t];
            }
            #pragma unroll 1
            for (; k < cnt; k++) n0 += u2e[(size_t)nb[k] * DIM + t];
            const float nsum = (n0 + n1) + (n2 + n3);
            partial = selfv * acc1[r] + nsum * (1.f / (float)cnt) * acc2[r] + bt * vrt;
        } else {
            partial = selfv * vrt;      // no-neighbor fallback: self . v
        }
        #pragma unroll
        for (int o = 16; o; o >>= 1)
            partial += __shfl_down_sync(0xffffffffu, partial, o);
        if ((t & 31) == 0) sred[r][t >> 5] = partial;
    }
    __syncthreads();

    if (t < RPB) {
        float s = 0.f;
        #pragma unroll
        for (int w = 0; w < 8; w++) s += sred[t][w];
        if (row0 + t < B) out[row0 + t] = s;
    }
}

extern "C" void kernel_launch(void* const* d_in, const int* in_sizes, int n_in,
                              void* d_out, int out_size)
{
    const int*   nodes_u         = (const int*)  d_in[0];
    const int*   nodes_v         = (const int*)  d_in[1];
    const int*   neighbors       = (const int*)  d_in[2];
    const int*   neighbor_counts = (const int*)  d_in[3];
    const float* u2e             = (const float*)d_in[4];
    const float* v2e             = (const float*)d_in[5];
    const float* W               = (const float*)d_in[6];
    const float* bvec            = (const float*)d_in[7];
    float*       out             = (float*)d_out;

    const int B = in_sizes[0];
    const int grid = (B + RPB - 1) / RPB;
    easyrec_fused<<<grid, NTHREADS>>>(nodes_u, nodes_v, neighbors, neighbor_counts,
                                      u2e, v2e, W, bvec, out, B);
}

// round 8
// speedup vs baseline: 1.8268x; 1.3527x over previous
#include <cuda_runtime.h>
#include <cuda_bf16.h>
#include <cstdint>

#define DIM      256
#define TWO_DIM  512
#define KMAX     64
#define B_MAX    16384

// ---------------- scratch (__device__ globals: allocation-guard-safe) ----------
__device__ __align__(128) __nv_bfloat16 g_Ahi[B_MAX * DIM];
__device__ __align__(128) __nv_bfloat16 g_Alo[B_MAX * DIM];
__device__ __align__(128) __nv_bfloat16 g_Whi[TWO_DIM * DIM];   // [n][k] = W[k][n]
__device__ __align__(128) __nv_bfloat16 g_Wlo[TWO_DIM * DIM];
__device__ __align__(128) float         g_H  [B_MAX * TWO_DIM];

// ---------------- portable MMA helpers (sm_80+; OK on compute_103) -------------
__device__ __forceinline__ uint32_t smem_u32(const void* p) {
    uint32_t a;
    asm("{ .reg .u64 t; cvta.to.shared.u64 t, %1; cvt.u32.u64 %0, t; }" : "=r"(a) : "l"(p));
    return a;
}
__device__ __forceinline__ void ldsm_x4(uint32_t (&r)[4], uint32_t addr) {
    asm volatile("ldmatrix.sync.aligned.m8n8.x4.shared.b16 {%0,%1,%2,%3}, [%4];"
                 : "=r"(r[0]), "=r"(r[1]), "=r"(r[2]), "=r"(r[3]) : "r"(addr));
}
__device__ __forceinline__ void ldsm_x2(uint32_t (&r)[2], uint32_t addr) {
    asm volatile("ldmatrix.sync.aligned.m8n8.x2.shared.b16 {%0,%1}, [%2];"
                 : "=r"(r[0]), "=r"(r[1]) : "r"(addr));
}
__device__ __forceinline__ void mma_bf16(float (&c)[4], const uint32_t (&a)[4],
                                         const uint32_t (&b)[2]) {
    asm volatile("mma.sync.aligned.m16n8k16.row.col.f32.bf16.bf16.f32 "
                 "{%0,%1,%2,%3}, {%4,%5,%6,%7}, {%8,%9}, {%0,%1,%2,%3};"
                 : "+f"(c[0]), "+f"(c[1]), "+f"(c[2]), "+f"(c[3])
                 : "r"(a[0]), "r"(a[1]), "r"(a[2]), "r"(a[3]), "r"(b[0]), "r"(b[1]));
}

// ---------------- Kernel 1a: W -> bf16 hi/lo, transposed [n][k] ----------------
__global__ __launch_bounds__(TWO_DIM)
void conv_w(const float* __restrict__ W) {
    const int k = blockIdx.x;       // 0..255
    const int n = threadIdx.x;      // 0..511
    const float x = W[(size_t)k * TWO_DIM + n];
    const __nv_bfloat16 hi = __float2bfloat16_rn(x);
    const __nv_bfloat16 lo = __float2bfloat16_rn(x - __bfloat162float(hi));
    g_Whi[(size_t)n * DIM + k] = hi;
    g_Wlo[(size_t)n * DIM + k] = lo;
}

// ---------------- Kernel 1b: gather v2e[nodes_v] -> bf16 hi/lo -----------------
__global__ __launch_bounds__(DIM)
void conv_a(const int* __restrict__ nodes_v, const float* __restrict__ v2e) {
    const int b = blockIdx.x;
    const int t = threadIdx.x;
    const int vi = nodes_v[b];
    const float x = v2e[(size_t)vi * DIM + t];
    const __nv_bfloat16 hi = __float2bfloat16_rn(x);
    const __nv_bfloat16 lo = __float2bfloat16_rn(x - __bfloat162float(hi));
    g_Ahi[(size_t)b * DIM + t] = hi;
    g_Alo[(size_t)b * DIM + t] = lo;
}

// ---------------- Kernel 2: H = A @ Wt^T via mma.sync bf16 3-way split ---------
// CTA tile 128x128, 8 warps (4 m-warps x 2 n-warps), warp tile 32m x 64n.
#define TM 128
#define TN 128
#define KC 32
#define SST 40   // smem k-stride in bf16 (80 B) -> conflict-free ldmatrix

__global__ __launch_bounds__(256)
void gemm_mma(int B) {
    __shared__ __nv_bfloat16 sAh[TM][SST], sAl[TM][SST];
    __shared__ __nv_bfloat16 sBh[TN][SST], sBl[TN][SST];

    const int t   = threadIdx.x;
    const int wid = t >> 5;
    const int lid = t & 31;
    const int wm  = wid & 3;            // 0..3 -> 32-row slice
    const int wn  = wid >> 2;           // 0..1 -> 64-col slice
    const int m0  = blockIdx.x * TM;
    const int n0  = blockIdx.y * TN;

    float acc[2][8][4];
    #pragma unroll
    for (int mf = 0; mf < 2; mf++)
        #pragma unroll
        for (int nf = 0; nf < 8; nf++)
            #pragma unroll
            for (int q = 0; q < 4; q++) acc[mf][nf][q] = 0.f;

    const uint32_t bAh = smem_u32(&sAh[0][0]);
    const uint32_t bAl = smem_u32(&sAl[0][0]);
    const uint32_t bBh = smem_u32(&sBh[0][0]);
    const uint32_t bBl = smem_u32(&sBl[0][0]);

    // per-lane ldmatrix row/k offsets
    const int a_row = lid & 15;                 // frag row 0..15
    const int a_kof = (lid & 16) ? 8 : 0;       // matrices 2/3 -> k+8
    const int b_row = lid & 7;
    const int b_kof = (lid & 8) ? 8 : 0;

    #pragma unroll 1
    for (int c = 0; c < DIM / KC; c++) {
        // ---- stage A (128x32) hi+lo ----
        #pragma unroll
        for (int i = t; i < TM * KC / 8; i += 256) {
            int row = i >> 2, kq = i & 3;
            int m = m0 + row; if (m >= B) m = B - 1;
            size_t src = (size_t)m * DIM + c * KC + kq * 8;
            *reinterpret_cast<uint4*>(&sAh[row][kq * 8]) = *reinterpret_cast<const uint4*>(&g_Ahi[src]);
            *reinterpret_cast<uint4*>(&sAl[row][kq * 8]) = *reinterpret_cast<const uint4*>(&g_Alo[src]);
        }
        // ---- stage B (128x32) hi+lo ----
        #pragma unroll
        for (int i = t; i < TN * KC / 8; i += 256) {
            int row = i >> 2, kq = i & 3;
            size_t src = (size_t)(n0 + row) * DIM + c * KC + kq * 8;
            *reinterpret_cast<uint4*>(&sBh[row][kq * 8]) = *reinterpret_cast<const uint4*>(&g_Whi[src]);
            *reinterpret_cast<uint4*>(&sBl[row][kq * 8]) = *reinterpret_cast<const uint4*>(&g_Wlo[src]);
        }
        __syncthreads();

        #pragma unroll
        for (int ks = 0; ks < KC / 16; ks++) {
            uint32_t ah[2][4], al[2][4];
            #pragma unroll
            for (int mf = 0; mf < 2; mf++) {
                uint32_t off = ((wm * 32 + mf * 16 + a_row) * SST + ks * 16 + a_kof) * 2;
                ldsm_x4(ah[mf], bAh + off);
                ldsm_x4(al[mf], bAl + off);
            }
            #pragma unroll
            for (int nf = 0; nf < 8; nf++) {
                uint32_t boff = ((wn * 64 + nf * 8 + b_row) * SST + ks * 16 + b_kof) * 2;
                uint32_t bh[2], bl[2];
                ldsm_x2(bh, bBh + boff);
                ldsm_x2(bl, bBl + boff);
                #pragma unroll
                for (int mf = 0; mf < 2; mf++) {
                    mma_bf16(acc[mf][nf], ah[mf], bh);   // hi*hi
                    mma_bf16(acc[mf][nf], ah[mf], bl);   // hi*lo
                    mma_bf16(acc[mf][nf], al[mf], bh);   // lo*hi
                }
            }
        }
        __syncthreads();
    }

    // ---- epilogue: c frag -> g_H ----
    const int rbase = m0 + wm * 32 + (lid >> 2);
    const int cbase = n0 + wn * 64 + (lid & 3) * 2;
    #pragma unroll
    for (int mf = 0; mf < 2; mf++) {
        #pragma unroll
        for (int nf = 0; nf < 8; nf++) {
            const int row = rbase + mf * 16;
            const int col = cbase + nf * 8;
            if (row < B) {
                float2 v0 = make_float2(acc[mf][nf][0], acc[mf][nf][1]);
                *reinterpret_cast<float2*>(&g_H[(size_t)row * TWO_DIM + col]) = v0;
            }
            if (row + 8 < B) {
                float2 v1 = make_float2(acc[mf][nf][2], acc[mf][nf][3]);
                *reinterpret_cast<float2*>(&g_H[(size_t)(row + 8) * TWO_DIM + col]) = v1;
            }
        }
    }
}

// ---------------- Kernel 3: gather + combine + reduce --------------------------
#define RPB 16
#define NTH 256

__global__ __launch_bounds__(NTH)
void combine(const int* __restrict__ nodes_u,
             const int* __restrict__ nodes_v,
             const int* __restrict__ neighbors,
             const int* __restrict__ neighbor_counts,
             const float* __restrict__ u2e,
             const float* __restrict__ v2e,
             const float* __restrict__ bvec,
             float* __restrict__ out,
             int B)
{
    __shared__ int   snb[RPB][KMAX];
    __shared__ int   scnt[RPB], su[RPB], svi[RPB], sbrow[RPB];
    __shared__ float sred[RPB][8];

    const int t    = threadIdx.x;
    const int row0 = blockIdx.x * RPB;

    for (int i = t; i < RPB * KMAX; i += NTH) {
        int r = i >> 6, k = i & 63;
        int b = row0 + r; if (b >= B) b = B - 1;
        snb[r][k] = neighbors[(size_t)b * KMAX + k];
    }
    if (t < RPB) {
        int b = row0 + t; if (b >= B) b = B - 1;
        scnt[t]  = neighbor_counts[b];
        su[t]    = nodes_u[b];
        svi[t]   = nodes_v[b];
        sbrow[t] = b;
    }
    __syncthreads();

    const float bt = bvec[t];

    #pragma unroll 1
    for (int r = 0; r < RPB; r++) {
        const int    cnt   = scnt[r];
        const size_t hb    = (size_t)sbrow[r] * TWO_DIM;
        const float  selfv = u2e[(size_t)su[r] * DIM + t];
        const float  vrt   = v2e[(size_t)svi[r] * DIM + t];
        const float  h1    = g_H[hb + t];
        const float  h2    = g_H[hb + DIM + t];
        float partial;
        if (cnt > 0) {
            const int* nb = snb[r];
            float n0 = 0.f, n1 = 0.f, n2 = 0.f, n3 = 0.f;
            int k = 0;
            #pragma unroll 1
            for (; k + 4 <= cnt; k += 4) {
                n0 += u2e[(size_t)nb[k + 0] * DIM + t];
                n1 += u2e[(size_t)nb[k + 1] * DIM + t];
                n2 += u2e[(size_t)nb[k + 2] * DIM + t];
                n3 += u2e[(size_t)nb[k + 3] * DIM + t];
            }
            #pragma unroll 1
            for (; k < cnt; k++) n0 += u2e[(size_t)nb[k] * DIM + t];
            const float nsum = (n0 + n1) + (n2 + n3);
            partial = selfv * h1 + nsum * (1.f / (float)cnt) * h2 + bt * vrt;
        } else {
            partial = selfv * vrt;          // no-neighbor fallback: self . v
        }
        #pragma unroll
        for (int o = 16; o; o >>= 1)
            partial += __shfl_down_sync(0xffffffffu, partial, o);
        if ((t & 31) == 0) sred[r][t >> 5] = partial;
    }
    __syncthreads();

    if (t < RPB) {
        float s = 0.f;
        #pragma unroll
        for (int w = 0; w < 8; w++) s += sred[t][w];
        if (row0 + t < B) out[row0 + t] = s;
    }
}

// ---------------- launch --------------------------------------------------------
extern "C" void kernel_launch(void* const* d_in, const int* in_sizes, int n_in,
                              void* d_out, int out_size)
{
    const int*   nodes_u         = (const int*)  d_in[0];
    const int*   nodes_v         = (const int*)  d_in[1];
    const int*   neighbors       = (const int*)  d_in[2];
    const int*   neighbor_counts = (const int*)  d_in[3];
    const float* u2e             = (const float*)d_in[4];
    const float* v2e             = (const float*)d_in[5];
    const float* W               = (const float*)d_in[6];
    const float* bvec            = (const float*)d_in[7];
    float*       out             = (float*)d_out;

    int B = in_sizes[0];
    if (B > B_MAX) B = B_MAX;

    conv_w<<<DIM, TWO_DIM>>>(W);
    conv_a<<<B, DIM>>>(nodes_v, v2e);
    dim3 ggrid((B + TM - 1) / TM, TWO_DIM / TN);
    gemm_mma<<<ggrid, 256>>>(B);
    combine<<<(B + RPB - 1) / RPB, NTH>>>(nodes_u, nodes_v, neighbors, neighbor_counts,
                                          u2e, v2e, bvec, out, B);
}

// round 9
// speedup vs baseline: 2.3503x; 1.2866x over previous
#include <cuda_runtime.h>
#include <cuda_bf16.h>
#include <cstdint>

#define DIM      256
#define TWO_DIM  512
#define KMAX     64
#define B_MAX    16384

// ---------------- scratch (__device__ globals: allocation-guard-safe) ----------
__device__ __align__(128) __nv_bfloat16 g_Ahi[B_MAX * DIM];
__device__ __align__(128) __nv_bfloat16 g_Alo[B_MAX * DIM];
__device__ __align__(128) __nv_bfloat16 g_Whi[TWO_DIM * DIM];   // [n][k] = W[k][n]
__device__ __align__(128) __nv_bfloat16 g_Wlo[TWO_DIM * DIM];
__device__ __align__(128) float         g_H  [B_MAX * TWO_DIM];

// ---------------- portable helpers (sm_80+; OK on compute_103) ----------------
__device__ __forceinline__ uint32_t smem_u32(const void* p) {
    uint32_t a;
    asm("{ .reg .u64 t; cvta.to.shared.u64 t, %1; cvt.u32.u64 %0, t; }" : "=r"(a) : "l"(p));
    return a;
}
__device__ __forceinline__ void ldsm_x4(uint32_t (&r)[4], uint32_t addr) {
    asm volatile("ldmatrix.sync.aligned.m8n8.x4.shared.b16 {%0,%1,%2,%3}, [%4];"
                 : "=r"(r[0]), "=r"(r[1]), "=r"(r[2]), "=r"(r[3]) : "r"(addr));
}
__device__ __forceinline__ void ldsm_x2(uint32_t (&r)[2], uint32_t addr) {
    asm volatile("ldmatrix.sync.aligned.m8n8.x2.shared.b16 {%0,%1}, [%2];"
                 : "=r"(r[0]), "=r"(r[1]) : "r"(addr));
}
__device__ __forceinline__ void mma_bf16(float (&c)[4], const uint32_t (&a)[4],
                                         const uint32_t (&b)[2]) {
    asm volatile("mma.sync.aligned.m16n8k16.row.col.f32.bf16.bf16.f32 "
                 "{%0,%1,%2,%3}, {%4,%5,%6,%7}, {%8,%9}, {%0,%1,%2,%3};"
                 : "+f"(c[0]), "+f"(c[1]), "+f"(c[2]), "+f"(c[3])
                 : "r"(a[0]), "r"(a[1]), "r"(a[2]), "r"(a[3]), "r"(b[0]), "r"(b[1]));
}
#define CP_ASYNC16(dst, src) \
    asm volatile("cp.async.cg.shared.global [%0], [%1], 16;" :: "r"(dst), "l"(src))
#define CP_COMMIT() asm volatile("cp.async.commit_group;" ::: "memory")
#define CP_WAIT(n)  asm volatile("cp.async.wait_group %0;" :: "n"(n) : "memory")

// ---------------- Kernel 1a: W -> bf16 hi/lo, transposed [n][k] ----------------
__global__ __launch_bounds__(TWO_DIM)
void conv_w(const float* __restrict__ W) {
    const int k = blockIdx.x;       // 0..255
    const int n = threadIdx.x;      // 0..511
    const float x = W[(size_t)k * TWO_DIM + n];
    const __nv_bfloat16 hi = __float2bfloat16_rn(x);
    const __nv_bfloat16 lo = __float2bfloat16_rn(x - __bfloat162float(hi));
    g_Whi[(size_t)n * DIM + k] = hi;
    g_Wlo[(size_t)n * DIM + k] = lo;
}

// ---------------- Kernel 1b: gather v2e[nodes_v] -> bf16 hi/lo -----------------
__global__ __launch_bounds__(DIM)
void conv_a(const int* __restrict__ nodes_v, const float* __restrict__ v2e) {
    const int b = blockIdx.x;
    const int t = threadIdx.x;
    const int vi = nodes_v[b];
    const float x = v2e[(size_t)vi * DIM + t];
    const __nv_bfloat16 hi = __float2bfloat16_rn(x);
    const __nv_bfloat16 lo = __float2bfloat16_rn(x - __bfloat162float(hi));
    g_Ahi[(size_t)b * DIM + t] = hi;
    g_Alo[(size_t)b * DIM + t] = lo;
}

// ---------------- Kernel 2: H = A @ Wt^T, mma.sync bf16 3-split, cp.async 2-stage
#define TM 128
#define TN 128
#define KC 32
#define SST 40                              // smem k-stride in bf16 (80 B)
#define ARR_B  (TM * SST * 2)               // 10240 B per array
#define STAGE_B (4 * ARR_B)                 // Ah, Al, Bh, Bl
#define GSMEM  (2 * STAGE_B)                // 81920 B
#define NC (DIM / KC)                       // 8

__global__ __launch_bounds__(256)
void gemm_mma(int B) {
    extern __shared__ char dsm[];
    const int t   = threadIdx.x;
    const int wid = t >> 5;
    const int lid = t & 31;
    const int wm  = wid & 3;
    const int wn  = wid >> 2;
    const int m0  = blockIdx.x * TM;
    const int n0  = blockIdx.y * TN;

    float acc[2][8][4];
    #pragma unroll
    for (int mf = 0; mf < 2; mf++)
        #pragma unroll
        for (int nf = 0; nf < 8; nf++)
            #pragma unroll
            for (int q = 0; q < 4; q++) acc[mf][nf][q] = 0.f;

    const uint32_t sbase = smem_u32(dsm);

    // issue cp.async staging for chunk c into stage s
    auto stage_load = [&](int c, int s) {
        const uint32_t so = sbase + s * STAGE_B;
        #pragma unroll
        for (int i = t; i < TM * KC / 8; i += 256) {       // 512 vec8 rows x hi/lo
            int row = i >> 2, kq = i & 3;
            int m = m0 + row; if (m >= B) m = B - 1;
            size_t src = (size_t)m * DIM + c * KC + kq * 8;
            uint32_t d = so + (row * SST + kq * 8) * 2;
            CP_ASYNC16(d,             &g_Ahi[src]);
            CP_ASYNC16(d + ARR_B,     &g_Alo[src]);
        }
        #pragma unroll
        for (int i = t; i < TN * KC / 8; i += 256) {
            int row = i >> 2, kq = i & 3;
            size_t src = (size_t)(n0 + row) * DIM + c * KC + kq * 8;
            uint32_t d = so + (row * SST + kq * 8) * 2;
            CP_ASYNC16(d + 2 * ARR_B, &g_Whi[src]);
            CP_ASYNC16(d + 3 * ARR_B, &g_Wlo[src]);
        }
        CP_COMMIT();
    };

    const int a_row = lid & 15;
    const int a_kof = (lid & 16) ? 8 : 0;
    const int b_row = lid & 7;
    const int b_kof = (lid & 8) ? 8 : 0;

    stage_load(0, 0);

    #pragma unroll 1
    for (int c = 0; c < NC; c++) {
        const int buf = c & 1;
        if (c + 1 < NC) stage_load(c + 1, buf ^ 1);
        if (c + 1 < NC) { CP_WAIT(1); } else { CP_WAIT(0); }
        __syncthreads();

        const uint32_t so  = sbase + buf * STAGE_B;
        const uint32_t bAh = so;
        const uint32_t bAl = so + ARR_B;
        const uint32_t bBh = so + 2 * ARR_B;
        const uint32_t bBl = so + 3 * ARR_B;

        #pragma unroll
        for (int ks = 0; ks < KC / 16; ks++) {
            uint32_t ah[2][4], al[2][4];
            #pragma unroll
            for (int mf = 0; mf < 2; mf++) {
                uint32_t off = ((wm * 32 + mf * 16 + a_row) * SST + ks * 16 + a_kof) * 2;
                ldsm_x4(ah[mf], bAh + off);
                ldsm_x4(al[mf], bAl + off);
            }
            #pragma unroll
            for (int nf = 0; nf < 8; nf++) {
                uint32_t boff = ((wn * 64 + nf * 8 + b_row) * SST + ks * 16 + b_kof) * 2;
                uint32_t bh[2], bl[2];
                ldsm_x2(bh, bBh + boff);
                ldsm_x2(bl, bBl + boff);
                #pragma unroll
                for (int mf = 0; mf < 2; mf++) {
                    mma_bf16(acc[mf][nf], ah[mf], bh);   // hi*hi
                    mma_bf16(acc[mf][nf], ah[mf], bl);   // hi*lo
                    mma_bf16(acc[mf][nf], al[mf], bh);   // lo*hi
                }
            }
        }
        __syncthreads();   // guard: next iter's load reuses this buf
    }

    const int rbase = m0 + wm * 32 + (lid >> 2);
    const int cbase = n0 + wn * 64 + (lid & 3) * 2;
    #pragma unroll
    for (int mf = 0; mf < 2; mf++) {
        #pragma unroll
        for (int nf = 0; nf < 8; nf++) {
            const int row = rbase + mf * 16;
            const int col = cbase + nf * 8;
            if (row < B)
                *reinterpret_cast<float2*>(&g_H[(size_t)row * TWO_DIM + col]) =
                    make_float2(acc[mf][nf][0], acc[mf][nf][1]);
            if (row + 8 < B)
                *reinterpret_cast<float2*>(&g_H[(size_t)(row + 8) * TWO_DIM + col]) =
                    make_float2(acc[mf][nf][2], acc[mf][nf][3]);
        }
    }
}

// ---------------- Kernel 3: gather + combine, float4 per thread ----------------
#define RPB 16
#define NTH 256

__global__ __launch_bounds__(NTH)
void combine(const int* __restrict__ nodes_u,
             const int* __restrict__ nodes_v,
             const int* __restrict__ neighbors,
             const int* __restrict__ neighbor_counts,
             const float* __restrict__ u2e,
             const float* __restrict__ v2e,
             const float* __restrict__ bvec,
             float* __restrict__ out,
             int B)
{
    __shared__ int   snb[RPB][KMAX];
    __shared__ int   scnt[RPB], su[RPB], svi[RPB], sbrow[RPB];
    __shared__ float sred[RPB][2];

    const int t    = threadIdx.x;
    const int gi   = t >> 6;          // group 0..3 (64 threads each)
    const int gt   = t & 63;
    const int c4   = gt * 4;          // this thread's 4 columns
    const int row0 = blockIdx.x * RPB;

    for (int i = t; i < RPB * KMAX; i += NTH) {
        int r = i >> 6, k = i & 63;
        int b = row0 + r; if (b >= B) b = B - 1;
        snb[r][k] = neighbors[(size_t)b * KMAX + k];
    }
    if (t < RPB) {
        int b = row0 + t; if (b >= B) b = B - 1;
        scnt[t]  = neighbor_counts[b];
        su[t]    = nodes_u[b];
        svi[t]   = nodes_v[b];
        sbrow[t] = b;
    }
    __syncthreads();

    const float4 b4 = *reinterpret_cast<const float4*>(&bvec[c4]);

    // each group handles 4 rows: r = gi*4 + rr
    #pragma unroll
    for (int rr = 0; rr < 4; rr++) {
        const int r   = gi * 4 + rr;
        const int cnt = scnt[r];
        const float4 self4 = *reinterpret_cast<const float4*>(&u2e[(size_t)su[r]  * DIM + c4]);
        const float4 v4    = *reinterpret_cast<const float4*>(&v2e[(size_t)svi[r] * DIM + c4]);
        float partial;
        if (cnt > 0) {
            const size_t hb = (size_t)sbrow[r] * TWO_DIM;
            const float4 h1 = *reinterpret_cast<const float4*>(&g_H[hb + c4]);
            const float4 h2 = *reinterpret_cast<const float4*>(&g_H[hb + DIM + c4]);
            const int* nb = snb[r];
            float4 a0 = make_float4(0, 0, 0, 0), a1 = a0, a2 = a0, a3 = a0;
            int k = 0;
            #pragma unroll 1
            for (; k + 4 <= cnt; k += 4) {       // 4 independent 16B chains
                float4 x0 = *reinterpret_cast<const float4*>(&u2e[(size_t)nb[k + 0] * DIM + c4]);
                float4 x1 = *reinterpret_cast<const float4*>(&u2e[(size_t)nb[k + 1] * DIM + c4]);
                float4 x2 = *reinterpret_cast<const float4*>(&u2e[(size_t)nb[k + 2] * DIM + c4]);
                float4 x3 = *reinterpret_cast<const float4*>(&u2e[(size_t)nb[k + 3] * DIM + c4]);
                a0.x += x0.x; a0.y += x0.y; a0.z += x0.z; a0.w += x0.w;
                a1.x += x1.x; a1.y += x1.y; a1.z += x1.z; a1.w += x1.w;
                a2.x += x2.x; a2.y += x2.y; a2.z += x2.z; a2.w += x2.w;
                a3.x += x3.x; a3.y += x3.y; a3.z += x3.z; a3.w += x3.w;
            }
            #pragma unroll 1
            for (; k < cnt; k++) {
                float4 x = *reinterpret_cast<const float4*>(&u2e[(size_t)nb[k] * DIM + c4]);
                a0.x += x.x; a0.y += x.y; a0.z += x.z; a0.w += x.w;
            }
            const float inv = 1.f / (float)cnt;
            float4 nm;
            nm.x = ((a0.x + a1.x) + (a2.x + a3.x)) * inv;
            nm.y = ((a0.y + a1.y) + (a2.y + a3.y)) * inv;
            nm.z = ((a0.z + a1.z) + (a2.z + a3.z)) * inv;
            nm.w = ((a0.w + a1.w) + (a2.w + a3.w)) * inv;
            partial = self4.x * h1.x + self4.y * h1.y + self4.z * h1.z + self4.w * h1.w
                    + nm.x    * h2.x + nm.y    * h2.y + nm.z    * h2.z + nm.w    * h2.w
                    + b4.x    * v4.x + b4.y    * v4.y + b4.z    * v4.z + b4.w    * v4.w;
        } else {
            partial = self4.x * v4.x + self4.y * v4.y + self4.z * v4.z + self4.w * v4.w;
        }
        #pragma unroll
        for (int o = 16; o; o >>= 1)
            partial += __shfl_down_sync(0xffffffffu, partial, o);
        if ((t & 31) == 0) sred[r][(t >> 5) & 1] = partial;
    }
    __syncthreads();

    if (t < RPB) {
        float s = sred[t][0] + sred[t][1];
        if (row0 + t < B) out[row0 + t] = s;
    }
}

// ---------------- launch --------------------------------------------------------
extern "C" void kernel_launch(void* const* d_in, const int* in_sizes, int n_in,
                              void* d_out, int out_size)
{
    const int*   nodes_u         = (const int*)  d_in[0];
    const int*   nodes_v         = (const int*)  d_in[1];
    const int*   neighbors       = (const int*)  d_in[2];
    const int*   neighbor_counts = (const int*)  d_in[3];
    const float* u2e             = (const float*)d_in[4];
    const float* v2e             = (const float*)d_in[5];
    const float* W               = (const float*)d_in[6];
    const float* bvec            = (const float*)d_in[7];
    float*       out             = (float*)d_out;

    int B = in_sizes[0];
    if (B > B_MAX) B = B_MAX;

    cudaFuncSetAttribute(gemm_mma, cudaFuncAttributeMaxDynamicSharedMemorySize, GSMEM);

    conv_w<<<DIM, TWO_DIM>>>(W);
    conv_a<<<B, DIM>>>(nodes_v, v2e);
    dim3 ggrid((B + TM - 1) / TM, TWO_DIM / TN);
    gemm_mma<<<ggrid, 256, GSMEM>>>(B);
    combine<<<(B + RPB - 1) / RPB, NTH>>>(nodes_u, nodes_v, neighbors, neighbor_counts,
                                          u2e, v2e, bvec, out, B);
}

// round 11
// speedup vs baseline: 2.6919x; 1.1453x over previous
#include <cuda_runtime.h>
#include <cuda_bf16.h>
#include <cstdint>

#define DIM      256
#define TWO_DIM  512
#define KMAX     64
#define B_MAX    16384
#define NMT      (B_MAX / 16)      // 1024 m-frag-tiles
#define NKT      (DIM / 16)        // 16 k-frag-tiles
#define NNT      (TWO_DIM / 8)     // 64 n-frag-tiles

// ---------------- scratch (__device__ globals: allocation-guard-safe) ----------
// A fragments: [mtile][ktile][lane][4 regs] of bf16x2 words, hi & lo
__device__ __align__(16) uint32_t g_Afh[NMT * NKT * 32 * 4];
__device__ __align__(16) uint32_t g_Afl[NMT * NKT * 32 * 4];
// W (B-operand) fragments: [ntile][ktile][lane][2 regs], hi & lo
__device__ __align__(16) uint32_t g_Wfh[NNT * NKT * 32 * 2];
__device__ __align__(16) uint32_t g_Wfl[NNT * NKT * 32 * 2];
__device__ __align__(128) float   g_H[B_MAX * TWO_DIM];

// ---------------- helpers ------------------------------------------------------
__device__ __forceinline__ uint32_t pack_bf16x2(float x0, float x1) {
    __nv_bfloat162 h = __floats2bfloat162_rn(x0, x1);   // low = x0, high = x1
    return *reinterpret_cast<uint32_t*>(&h);
}
__device__ __forceinline__ void mma_bf16(float (&c)[4], const uint32_t* a,
                                         const uint32_t* b) {
    asm volatile("mma.sync.aligned.m16n8k16.row.col.f32.bf16.bf16.f32 "
                 "{%0,%1,%2,%3}, {%4,%5,%6,%7}, {%8,%9}, {%0,%1,%2,%3};"
                 : "+f"(c[0]), "+f"(c[1]), "+f"(c[2]), "+f"(c[3])
                 : "r"(a[0]), "r"(a[1]), "r"(a[2]), "r"(a[3]), "r"(b[0]), "r"(b[1]));
}

// ---------------- Kernel 1a: W -> B-operand fragments (hi/lo) ------------------
// b-frag reg r (r=0,1): k = kt*16 + (l&3)*2 + r*8 (pair k, k+1), n = nt*8 + (l>>2)
__global__ __launch_bounds__(256)
void conv_w(const float* __restrict__ W) {
    const int l   = threadIdx.x & 31;
    const int wid = threadIdx.x >> 5;
    const int nt  = blockIdx.x >> 1;
    const int kt  = ((blockIdx.x & 1) << 3) + wid;
    const int n   = nt * 8 + (l >> 2);
    uint2 hi, lo;
    #pragma unroll
    for (int r = 0; r < 2; r++) {
        const int k = kt * 16 + ((l & 3) << 1) + (r << 3);
        const float x0 = W[(size_t)k * TWO_DIM + n];
        const float x1 = W[(size_t)(k + 1) * TWO_DIM + n];
        const float h0 = __bfloat162float(__float2bfloat16_rn(x0));
        const float h1 = __bfloat162float(__float2bfloat16_rn(x1));
        (&hi.x)[r] = pack_bf16x2(x0, x1);
        (&lo.x)[r] = pack_bf16x2(x0 - h0, x1 - h1);
    }
    const size_t idx = ((size_t)nt * NKT + kt) * 32 + l;
    reinterpret_cast<uint2*>(g_Wfh)[idx] = hi;
    reinterpret_cast<uint2*>(g_Wfl)[idx] = lo;
}

// ---------------- Kernel 1b: gather v2e[nodes_v] -> A fragments (hi/lo) --------
// a-frag reg r: row = (l>>2) + (r&1)*8, col(k) = (l&3)*2 + ((r&2)?8:0) (pair)
__global__ __launch_bounds__(256)
void conv_a(const int* __restrict__ nodes_v, const float* __restrict__ v2e, int B) {
    const int mt  = blockIdx.x;
    const int l   = threadIdx.x & 31;
    const int wid = threadIdx.x >> 5;
    #pragma unroll 1
    for (int kt = wid; kt < NKT; kt += 8) {
        uint4 hi, lo;
        #pragma unroll
        for (int r = 0; r < 4; r++) {
            const int row = (l >> 2) + ((r & 1) << 3);
            const int col = ((l & 3) << 1) + ((r & 2) << 2);
            int b = mt * 16 + row; if (b >= B) b = B - 1;
            const int vi = nodes_v[b];
            const float x0 = v2e[(size_t)vi * DIM + kt * 16 + col];
            const float x1 = v2e[(size_t)vi * DIM + kt * 16 + col + 1];
            const float h0 = __bfloat162float(__float2bfloat16_rn(x0));
            const float h1 = __bfloat162float(__float2bfloat16_rn(x1));
            (&hi.x)[r] = pack_bf16x2(x0, x1);
            (&lo.x)[r] = pack_bf16x2(x0 - h0, x1 - h1);
        }
        const size_t idx = ((size_t)mt * NKT + kt) * 32 + l;
        reinterpret_cast<uint4*>(g_Afh)[idx] = hi;
        reinterpret_cast<uint4*>(g_Afl)[idx] = lo;
    }
}

// ---------------- Kernel 2: H = A @ Wt^T, frag-direct (no smem, no syncs) ------
// CTA: 8 warps, tile 128m x 128n. Warp: 32m (2 mtiles) x 64n (8 ntiles).
__global__ __launch_bounds__(256)
void gemm_mma(int B) {
    const int t   = threadIdx.x;
    const int wid = t >> 5;
    const int lid = t & 31;
    const int wm  = wid & 3;
    const int wn  = wid >> 2;
    const int m0t = blockIdx.x * 8;       // base mtile
    const int n0t = blockIdx.y * 16;      // base ntile

    float acc[2][8][4];
    #pragma unroll
    for (int mf = 0; mf < 2; mf++)
        #pragma unroll
        for (int nf = 0; nf < 8; nf++)
            #pragma unroll
            for (int q = 0; q < 4; q++) acc[mf][nf][q] = 0.f;

    const uint4* Afh4 = reinterpret_cast<const uint4*>(g_Afh);
    const uint4* Afl4 = reinterpret_cast<const uint4*>(g_Afl);
    const uint2* Wfh2 = reinterpret_cast<const uint2*>(g_Wfh);
    const uint2* Wfl2 = reinterpret_cast<const uint2*>(g_Wfl);

    #pragma unroll 2
    for (int kt = 0; kt < NKT; kt++) {
        uint4 ah[2], al[2];
        #pragma unroll
        for (int mf = 0; mf < 2; mf++) {
            const size_t ai = ((size_t)(m0t + wm * 2 + mf) * NKT + kt) * 32 + lid;
            ah[mf] = Afh4[ai];
            al[mf] = Afl4[ai];
        }
        #pragma unroll
        for (int nf = 0; nf < 8; nf++) {
            const size_t bi = ((size_t)(n0t + wn * 8 + nf) * NKT + kt) * 32 + lid;
            const uint2 bh = Wfh2[bi];
            const uint2 bl = Wfl2[bi];
            #pragma unroll
            for (int mf = 0; mf < 2; mf++) {
                mma_bf16(acc[mf][nf], &ah[mf].x, &bh.x);   // hi*hi
                mma_bf16(acc[mf][nf], &ah[mf].x, &bl.x);   // hi*lo
                mma_bf16(acc[mf][nf], &al[mf].x, &bh.x);   // lo*hi
            }
        }
    }

    const int rbase = blockIdx.x * 128 + wm * 32 + (lid >> 2);
    const int cbase = blockIdx.y * 128 + wn * 64 + (lid & 3) * 2;
    #pragma unroll
    for (int mf = 0; mf < 2; mf++) {
        #pragma unroll
        for (int nf = 0; nf < 8; nf++) {
            const int row = rbase + mf * 16;
            const int col = cbase + nf * 8;
            if (row < B)
                *reinterpret_cast<float2*>(&g_H[(size_t)row * TWO_DIM + col]) =
                    make_float2(acc[mf][nf][0], acc[mf][nf][1]);
            if (row + 8 < B)
                *reinterpret_cast<float2*>(&g_H[(size_t)(row + 8) * TWO_DIM + col]) =
                    make_float2(acc[mf][nf][2], acc[mf][nf][3]);
        }
    }
}

// ---------------- Kernel 3: gather + combine, float4/thread, MLP 8 -------------
#define RPB 16
#define NTH 256

__global__ __launch_bounds__(NTH)
void combine(const int* __restrict__ nodes_u,
             const int* __restrict__ nodes_v,
             const int* __restrict__ neighbors,
             const int* __restrict__ neighbor_counts,
             const float* __restrict__ u2e,
             const float* __restrict__ v2e,
             const float* __restrict__ bvec,
             float* __restrict__ out,
             int B)
{
    __shared__ int   snb[RPB][KMAX];
    __shared__ int   scnt[RPB], su[RPB], svi[RPB], sbrow[RPB];
    __shared__ float sred[RPB][2];

    const int t    = threadIdx.x;
    const int gi   = t >> 6;          // group 0..3 (64 threads)
    const int gt   = t & 63;
    const int c4   = gt * 4;
    const int row0 = blockIdx.x * RPB;

    for (int i = t; i < RPB * KMAX; i += NTH) {
        int r = i >> 6, k = i & 63;
        int b = row0 + r; if (b >= B) b = B - 1;
        snb[r][k] = neighbors[(size_t)b * KMAX + k];
    }
    if (t < RPB) {
        int b = row0 + t; if (b >= B) b = B - 1;
        scnt[t]  = neighbor_counts[b];
        su[t]    = nodes_u[b];
        svi[t]   = nodes_v[b];
        sbrow[t] = b;
    }
    __syncthreads();

    const float4 b4 = *reinterpret_cast<const float4*>(&bvec[c4]);

    #pragma unroll
    for (int rr = 0; rr < 4; rr++) {
        const int r   = gi * 4 + rr;
        const int cnt = scnt[r];
        const float4 self4 = *reinterpret_cast<const float4*>(&u2e[(size_t)su[r]  * DIM + c4]);
        const float4 v4    = *reinterpret_cast<const float4*>(&v2e[(size_t)svi[r] * DIM + c4]);
        float partial;
        if (cnt > 0) {
            const size_t hb = (size_t)sbrow[r] * TWO_DIM;
            const float4 h1 = *reinterpret_cast<const float4*>(&g_H[hb + c4]);
            const float4 h2 = *reinterpret_cast<const float4*>(&g_H[hb + DIM + c4]);
            const int* nb = snb[r];
            float4 a0 = make_float4(0, 0, 0, 0), a1 = a0;
            int k = 0;
            #pragma unroll 1
            for (; k + 8 <= cnt; k += 8) {      // 8 independent 16B loads in flight
                float4 x0 = *reinterpret_cast<const float4*>(&u2e[(size_t)nb[k + 0] * DIM + c4]);
                float4 x1 = *reinterpret_cast<const float4*>(&u2e[(size_t)nb[k + 1] * DIM + c4]);
                float4 x2 = *reinterpret_cast<const float4*>(&u2e[(size_t)nb[k + 2] * DIM + c4]);
                float4 x3 = *reinterpret_cast<const float4*>(&u2e[(size_t)nb[k + 3] * DIM + c4]);
                float4 x4 = *reinterpret_cast<const float4*>(&u2e[(size_t)nb[k + 4] * DIM + c4]);
                float4 x5 = *reinterpret_cast<const float4*>(&u2e[(size_t)nb[k + 5] * DIM + c4]);
                float4 x6 = *reinterpret_cast<const float4*>(&u2e[(size_t)nb[k + 6] * DIM + c4]);
                float4 x7 = *reinterpret_cast<const float4*>(&u2e[(size_t)nb[k + 7] * DIM + c4]);
                a0.x += x0.x; a0.y += x0.y; a0.z += x0.z; a0.w += x0.w;
                a1.x += x1.x; a1.y += x1.y; a1.z += x1.z; a1.w += x1.w;
                a0.x += x2.x; a0.y += x2.y; a0.z += x2.z; a0.w += x2.w;
                a1.x += x3.x; a1.y += x3.y; a1.z += x3.z; a1.w += x3.w;
                a0.x += x4.x; a0.y += x4.y; a0.z += x4.z; a0.w += x4.w;
                a1.x += x5.x; a1.y += x5.y; a1.z += x5.z; a1.w += x5.w;
                a0.x += x6.x; a0.y += x6.y; a0.z += x6.z; a0.w += x6.w;
                a1.x += x7.x; a1.y += x7.y; a1.z += x7.z; a1.w += x7.w;
            }
            #pragma unroll 1
            for (; k < cnt; k++) {
                float4 x = *reinterpret_cast<const float4*>(&u2e[(size_t)nb[k] * DIM + c4]);
                a0.x += x.x; a0.y += x.y; a0.z += x.z; a0.w += x.w;
            }
            const float inv = 1.f / (float)cnt;
            float4 nm;
            nm.x = (a0.x + a1.x) * inv;
            nm.y = (a0.y + a1.y) * inv;
            nm.z = (a0.z + a1.z) * inv;
            nm.w = (a0.w + a1.w) * inv;
            partial = self4.x * h1.x + self4.y * h1.y + self4.z * h1.z + self4.w * h1.w
                    + nm.x    * h2.x + nm.y    * h2.y + nm.z    * h2.z + nm.w    * h2.w
                    + b4.x    * v4.x + b4.y    * v4.y + b4.z    * v4.z + b4.w    * v4.w;
        } else {
            partial = self4.x * v4.x + self4.y * v4.y + self4.z * v4.z + self4.w * v4.w;
        }
        #pragma unroll
        for (int o = 16; o; o >>= 1)
            partial += __shfl_down_sync(0xffffffffu, partial, o);
        if ((t & 31) == 0) sred[r][(t >> 5) & 1] = partial;
    }
    __syncthreads();

    if (t < RPB) {
        float s = sred[t][0] + sred[t][1];
        if (row0 + t < B) out[row0 + t] = s;
    }
}

// ---------------- launch --------------------------------------------------------
extern "C" void kernel_launch(void* const* d_in, const int* in_sizes, int n_in,
                              void* d_out, int out_size)
{
    const int*   nodes_u         = (const int*)  d_in[0];
    const int*   nodes_v         = (const int*)  d_in[1];
    const int*   neighbors       = (const int*)  d_in[2];
    const int*   neighbor_counts = (const int*)  d_in[3];
    const float* u2e             = (const float*)d_in[4];
    const float* v2e             = (const float*)d_in[5];
    const float* W               = (const float*)d_in[6];
    const float* bvec            = (const float*)d_in[7];
    float*       out             = (float*)d_out;

    int B = in_sizes[0];
    if (B > B_MAX) B = B_MAX;
    const int nmt = (B + 15) / 16;

    conv_w<<<128, 256>>>(W);
    conv_a<<<nmt, 256>>>(nodes_v, v2e, B);
    dim3 ggrid((B + 127) / 128, TWO_DIM / 128);
    gemm_mma<<<ggrid, 256>>>(B);
    combine<<<(B + RPB - 1) / RPB, NTH>>>(nodes_u, nodes_v, neighbors, neighbor_counts,
                                          u2e, v2e, bvec, out, B);
}